// round 1
// baseline (speedup 1.0000x reference)
#include <cuda_runtime.h>

#define SEQ 2048
#define HD  64
#define NBH 32      // B*H = 2*16
#define NHEAD 16

// per-row softmax denominators, written by K1, read by K2
__device__ float g_l[NBH * SEQ];

// ---------------------------------------------------------------------------
// K1: E = exp(mask(Q K^T / 8)) for lower-triangular tiles, plus exact row sums.
// One block = (bh, qtile of 128 rows); loops over its <=16 ktiles of 128.
// smem: Qs[64][132] + Ks[64][132] (transposed [d][row]) = 67584 B dynamic.
// ---------------------------------------------------------------------------
__global__ __launch_bounds__(256) void attn_scores_kernel(
    const float* __restrict__ Q, const float* __restrict__ K,
    const float* __restrict__ mask, const int* __restrict__ mask_now,
    float* __restrict__ E)
{
    const int qt  = blockIdx.x;
    const int bh  = blockIdx.y;
    const int tid = threadIdx.x;
    const int tx  = tid & 15;      // key cols, micro 8
    const int ty  = tid >> 4;      // query rows, micro 8

    extern __shared__ float sm[];
    float* Qs = sm;                // [64][132]
    float* Ks = sm + 64 * 132;     // [64][132]

    const int b  = bh >> 4;        // batch index (bh = b*16 + h)
    const int mn = mask_now[0];
    const int q0 = qt * 128;

    // Load Q tile transposed: Qs[d][q]
    {
        const float4* Qg = (const float4*)(Q + ((size_t)bh * SEQ + q0) * HD);
        for (int i = tid; i < 128 * 16; i += 256) {
            int q = i >> 4, dc = i & 15;
            float4 v = Qg[q * 16 + dc];
            int d = dc * 4;
            Qs[(d + 0) * 132 + q] = v.x;
            Qs[(d + 1) * 132 + q] = v.y;
            Qs[(d + 2) * 132 + q] = v.z;
            Qs[(d + 3) * 132 + q] = v.w;
        }
    }

    float rowmask[8];
    #pragma unroll
    for (int i = 0; i < 8; i++)
        rowmask[i] = mask[(size_t)b * SEQ + q0 + ty * 8 + i];

    float rowsum[8];
    #pragma unroll
    for (int i = 0; i < 8; i++) rowsum[i] = 0.f;

    for (int kt = 0; kt <= qt; kt++) {
        __syncthreads();   // previous compute done reading Ks
        const int k0 = kt * 128;
        {
            const float4* Kg = (const float4*)(K + ((size_t)bh * SEQ + k0) * HD);
            for (int i = tid; i < 128 * 16; i += 256) {
                int k = i >> 4, dc = i & 15;
                float4 v = Kg[k * 16 + dc];
                int d = dc * 4;
                Ks[(d + 0) * 132 + k] = v.x;
                Ks[(d + 1) * 132 + k] = v.y;
                Ks[(d + 2) * 132 + k] = v.z;
                Ks[(d + 3) * 132 + k] = v.w;
            }
        }
        __syncthreads();

        float acc[8][8];
        #pragma unroll
        for (int i = 0; i < 8; i++)
            #pragma unroll
            for (int j = 0; j < 8; j++) acc[i][j] = 0.f;

        #pragma unroll 4
        for (int d = 0; d < 64; d++) {
            float4 a0 = *(const float4*)&Qs[d * 132 + ty * 8];
            float4 a1 = *(const float4*)&Qs[d * 132 + ty * 8 + 4];
            float4 b0 = *(const float4*)&Ks[d * 132 + tx * 8];
            float4 b1 = *(const float4*)&Ks[d * 132 + tx * 8 + 4];
            float a[8] = {a0.x, a0.y, a0.z, a0.w, a1.x, a1.y, a1.z, a1.w};
            float bb[8] = {b0.x, b0.y, b0.z, b0.w, b1.x, b1.y, b1.z, b1.w};
            #pragma unroll
            for (int i = 0; i < 8; i++)
                #pragma unroll
                for (int j = 0; j < 8; j++)
                    acc[i][j] = fmaf(a[i], bb[j], acc[i][j]);
        }

        // mask + exp + rowsum + store
        #pragma unroll
        for (int i = 0; i < 8; i++) {
            const int q = q0 + ty * 8 + i;
            float ev[8];
            #pragma unroll
            for (int j = 0; j < 8; j++) {
                const int k = k0 + tx * 8 + j;
                const bool keep = (k + mn <= q) && (rowmask[i] != 0.f);
                float e = keep ? __expf(acc[i][j] * 0.125f) : 0.f;
                ev[j] = e;
                rowsum[i] += e;
            }
            float* dst = E + ((size_t)bh * SEQ + q) * SEQ + k0 + tx * 8;
            *(float4*)(dst)     = make_float4(ev[0], ev[1], ev[2], ev[3]);
            *(float4*)(dst + 4) = make_float4(ev[4], ev[5], ev[6], ev[7]);
        }
    }

    // reduce rowsum across the 16 tx lanes (same ty within each 16-lane group)
    #pragma unroll
    for (int i = 0; i < 8; i++) {
        float v = rowsum[i];
        #pragma unroll
        for (int off = 8; off; off >>= 1)
            v += __shfl_xor_sync(0xffffffffu, v, off);
        if (tx == 0)
            g_l[bh * SEQ + q0 + ty * 8 + i] = v;
    }
}

// ---------------------------------------------------------------------------
// K2: in-place normalize P = E / l on the causal part, write exact zeros above
// the diagonal (never reads unwritten/poisoned memory). One block per row.
// ---------------------------------------------------------------------------
__global__ __launch_bounds__(256) void attn_norm_kernel(
    const int* __restrict__ mask_now, float* __restrict__ P)
{
    const int row = blockIdx.x;            // bh*SEQ + q
    const int q   = row & (SEQ - 1);
    const float l = g_l[row];
    const float inv = (l > 0.f) ? (1.f / l) : 0.f;
    const int kmax = q - mask_now[0];      // keep k <= kmax

    float4* ptr = (float4*)(P + (size_t)row * SEQ);
    for (int t = threadIdx.x; t < SEQ / 4; t += 256) {
        const int k0 = t * 4;
        float4 v;
        if (k0 <= kmax) {                  // whole float4 lies in a written tile
            v = ptr[t];
            v.x *= inv; v.y *= inv; v.z *= inv; v.w *= inv;
        } else {
            v = make_float4(0.f, 0.f, 0.f, 0.f);
        }
        ptr[t] = v;
    }
}

// ---------------------------------------------------------------------------
// K3: O = P @ V over the causal region. One block = (bh, qtile of 128).
// ktiles of 64. smem: Ps[64][132] (transposed [k][q]) + Vs[64][68] = 51200 B.
// ---------------------------------------------------------------------------
__global__ __launch_bounds__(256) void attn_pv_kernel(
    const float* __restrict__ V, const float* __restrict__ P,
    float* __restrict__ O)
{
    const int qt  = blockIdx.x;
    const int bh  = blockIdx.y;
    const int tid = threadIdx.x;
    const int tx  = tid & 15;     // d cols, micro 4 -> 64
    const int ty  = tid >> 4;     // q rows, micro 8 -> 128

    extern __shared__ float sm[];
    float* Ps = sm;               // [64][132]  ([k][q])
    float* Vs = sm + 64 * 132;    // [64][68]   ([k][d])

    const int q0 = qt * 128;

    float acc[8][4];
    #pragma unroll
    for (int i = 0; i < 8; i++)
        #pragma unroll
        for (int j = 0; j < 4; j++) acc[i][j] = 0.f;

    const int ktmax = 2 * qt + 1;          // 64-wide ktiles covering k <= q0+127

    for (int kt = 0; kt <= ktmax; kt++) {
        __syncthreads();
        const int k0 = kt * 64;

        // load P tile transposed: P[q][k] -> Ps[k][q]
        for (int i = tid; i < 128 * 16; i += 256) {
            int q = i >> 4, kc = i & 15;
            float4 v = *(const float4*)(P + ((size_t)bh * SEQ + q0 + q) * SEQ + k0 + kc * 4);
            int k = kc * 4;
            Ps[(k + 0) * 132 + q] = v.x;
            Ps[(k + 1) * 132 + q] = v.y;
            Ps[(k + 2) * 132 + q] = v.z;
            Ps[(k + 3) * 132 + q] = v.w;
        }
        // load V tile: Vs[k][d]
        for (int i = tid; i < 64 * 16; i += 256) {
            int k = i >> 4, dc = i & 15;
            *(float4*)&Vs[k * 68 + dc * 4] =
                *(const float4*)(V + ((size_t)bh * SEQ + k0 + k) * HD + dc * 4);
        }
        __syncthreads();

        #pragma unroll 8
        for (int k = 0; k < 64; k++) {
            float4 bv = *(const float4*)&Vs[k * 68 + tx * 4];
            float4 a0 = *(const float4*)&Ps[k * 132 + ty * 8];
            float4 a1 = *(const float4*)&Ps[k * 132 + ty * 8 + 4];
            float a[8] = {a0.x, a0.y, a0.z, a0.w, a1.x, a1.y, a1.z, a1.w};
            float bb[4] = {bv.x, bv.y, bv.z, bv.w};
            #pragma unroll
            for (int i = 0; i < 8; i++)
                #pragma unroll
                for (int j = 0; j < 4; j++)
                    acc[i][j] = fmaf(a[i], bb[j], acc[i][j]);
        }
    }

    #pragma unroll
    for (int i = 0; i < 8; i++) {
        float* dst = O + ((size_t)bh * SEQ + q0 + ty * 8 + i) * HD + tx * 4;
        *(float4*)dst = make_float4(acc[i][0], acc[i][1], acc[i][2], acc[i][3]);
    }
}

// ---------------------------------------------------------------------------
extern "C" void kernel_launch(void* const* d_in, const int* in_sizes, int n_in,
                              void* d_out, int out_size)
{
    const float* Q        = (const float*)d_in[0];
    const float* K        = (const float*)d_in[1];
    const float* V        = (const float*)d_in[2];
    const float* mask     = (const float*)d_in[3];
    const int*   mask_now = (const int*)d_in[4];

    float* O = (float*)d_out;                        // [B,H,S,D]
    float* P = O + (size_t)NBH * SEQ * HD;           // [B,H,S,S] attn scores

    // >48KB dynamic smem kernels need the attribute; idempotent, capture-safe.
    cudaFuncSetAttribute(attn_scores_kernel,
                         cudaFuncAttributeMaxDynamicSharedMemorySize, 67584);
    cudaFuncSetAttribute(attn_pv_kernel,
                         cudaFuncAttributeMaxDynamicSharedMemorySize, 51200);

    attn_scores_kernel<<<dim3(16, NBH), 256, 67584>>>(Q, K, mask, mask_now, P);
    attn_norm_kernel<<<NBH * SEQ, 256>>>(mask_now, P);
    attn_pv_kernel<<<dim3(16, NBH), 256, 51200>>>(V, P, O);
}

// round 3
// speedup vs baseline: 2.0556x; 2.0556x over previous
#include <cuda_runtime.h>
#include <cuda_bf16.h>
#include <cstdint>

#define SEQ 2048
#define HD  64
#define NBH 32

// per-row softmax denominators, written by k_attn, read by k_norm
__device__ float g_l[NBH * SEQ];

#define SWZ(x) ((x) ^ (((x) >> 3) & 0x70))

__device__ __forceinline__ uint32_t smem_u32(const void* p) {
    uint32_t a;
    asm("{ .reg .u64 t; cvta.to.shared.u64 t, %1; cvt.u32.u64 %0, t; }"
        : "=r"(a) : "l"(p));
    return a;
}
__device__ __forceinline__ void ldsm4(uint32_t* d, uint32_t a) {
    asm volatile("ldmatrix.sync.aligned.m8n8.x4.shared.b16 {%0,%1,%2,%3}, [%4];"
        : "=r"(d[0]), "=r"(d[1]), "=r"(d[2]), "=r"(d[3]) : "r"(a));
}
__device__ __forceinline__ void ldsm4t(uint32_t* d, uint32_t a) {
    asm volatile("ldmatrix.sync.aligned.m8n8.x4.trans.shared.b16 {%0,%1,%2,%3}, [%4];"
        : "=r"(d[0]), "=r"(d[1]), "=r"(d[2]), "=r"(d[3]) : "r"(a));
}
__device__ __forceinline__ void mma_bf16(float* c, const uint32_t* a,
                                         uint32_t b0, uint32_t b1) {
    asm volatile(
        "mma.sync.aligned.m16n8k16.row.col.f32.bf16.bf16.f32 "
        "{%0,%1,%2,%3}, {%4,%5,%6,%7}, {%8,%9}, {%0,%1,%2,%3};"
        : "+f"(c[0]), "+f"(c[1]), "+f"(c[2]), "+f"(c[3])
        : "r"(a[0]), "r"(a[1]), "r"(a[2]), "r"(a[3]), "r"(b0), "r"(b1));
}
// split a pair of fp32 into packed-bf16 hi word and residual-lo word
__device__ __forceinline__ void split2(float x0, float x1, uint32_t& hi, uint32_t& lo) {
    __nv_bfloat162 h = __floats2bfloat162_rn(x0, x1);   // .x = x0 (low half)
    float r0 = x0 - __bfloat162float(h.x);
    float r1 = x1 - __bfloat162float(h.y);
    __nv_bfloat162 l = __floats2bfloat162_rn(r0, r1);
    hi = *reinterpret_cast<uint32_t*>(&h);
    lo = *reinterpret_cast<uint32_t*>(&l);
}

// ---------------------------------------------------------------------------
// Fused: E = exp(mask(QK^T/8)) stored to gmem, rowsums -> g_l,
// O = (E @ V) / l. Block = 512 thr (16 warps: 8 M-rows x 2 N-halves),
// tile M=128 q, N=128 k per iter, d=64.
// smem planes (bf16, SW128, [row][64]): QHI 0, QLO 16K, KHI 32K, KLO 48K,
// VHI 64K, VLO 80K; RS @96K (256 f), INV @97.25K (128 f); Obuf reuses @32K.
// ---------------------------------------------------------------------------
__global__ __launch_bounds__(512, 1) void k_attn(
    const float* __restrict__ Q, const float* __restrict__ K,
    const float* __restrict__ V, const float* __restrict__ mask,
    const int* __restrict__ mask_now,
    float* __restrict__ E, float* __restrict__ O)
{
    extern __shared__ char sm[];
    const uint32_t smb = smem_u32(sm);
    const int tid = threadIdx.x, lane = tid & 31, warp = tid >> 5;
    const int mrow = warp >> 1, nhalf = warp & 1;
    const int g = lane >> 3, r8 = lane & 7;
    const int qt = 15 - blockIdx.x, bh = blockIdx.y, b = bh >> 4;
    const int q0 = qt * 128;
    const int mn = mask_now[0];

    const uint32_t QHI = 0, QLO = 16384, KHI = 32768, KLO = 49152,
                   VHI = 65536, VLO = 81920;
    float* RS  = (float*)(sm + 98304);
    float* INV = (float*)(sm + 99328);
    float* Ob  = (float*)(sm + 32768);   // reused after mainloop

    // stage Q (pre-scaled by 1/8) into bf16 hi/lo planes
    {
        const float* Qg = Q + ((size_t)bh * SEQ + q0) * HD;
        for (int i = tid; i < 2048; i += 512) {
            int row = i >> 4, c4 = i & 15;
            float4 v = *(const float4*)(Qg + row * HD + c4 * 4);
            uint32_t h0, l0, h1, l1;
            split2(v.x * 0.125f, v.y * 0.125f, h0, l0);
            split2(v.z * 0.125f, v.w * 0.125f, h1, l1);
            uint32_t off = SWZ(row * 128 + c4 * 8);
            *(uint2*)(sm + QHI + off) = make_uint2(h0, h1);
            *(uint2*)(sm + QLO + off) = make_uint2(l0, l1);
        }
    }

    const int rl = mrow * 16 + (lane >> 2), rh = rl + 8;   // local q rows
    const int qrl = q0 + rl, qrh = q0 + rh;
    const bool mql = mask[(size_t)b * SEQ + qrl] != 0.f;
    const bool mqh = mask[(size_t)b * SEQ + qrh] != 0.f;

    float o[8][4];
    #pragma unroll
    for (int j = 0; j < 8; j++)
        o[j][0] = o[j][1] = o[j][2] = o[j][3] = 0.f;
    float rsl = 0.f, rsh = 0.f;

    for (int t = 0; t <= qt; t++) {
        const int k0 = t * 128;
        __syncthreads();                    // prev iter done reading K/V planes
        {
            const float* Kg = K + ((size_t)bh * SEQ + k0) * HD;
            const float* Vg = V + ((size_t)bh * SEQ + k0) * HD;
            for (int i = tid; i < 2048; i += 512) {
                int row = i >> 4, c4 = i & 15;
                uint32_t off = SWZ(row * 128 + c4 * 8);
                float4 v = *(const float4*)(Kg + row * HD + c4 * 4);
                uint32_t h0, l0, h1, l1;
                split2(v.x, v.y, h0, l0); split2(v.z, v.w, h1, l1);
                *(uint2*)(sm + KHI + off) = make_uint2(h0, h1);
                *(uint2*)(sm + KLO + off) = make_uint2(l0, l1);
                v = *(const float4*)(Vg + row * HD + c4 * 4);
                split2(v.x, v.y, h0, l0); split2(v.z, v.w, h1, l1);
                *(uint2*)(sm + VHI + off) = make_uint2(h0, h1);
                *(uint2*)(sm + VLO + off) = make_uint2(l0, l1);
            }
        }
        __syncthreads();

        const bool diag = (t == qt);
        const int kb = k0 + nhalf * 64 + 2 * (lane & 3);

        // two halves of the n64 warp tile to cap register pressure
        #pragma unroll
        for (int h = 0; h < 2; h++) {
            float c[4][4];
            #pragma unroll
            for (int j = 0; j < 4; j++)
                c[j][0] = c[j][1] = c[j][2] = c[j][3] = 0.f;

            // ---- QK^T (bf16 x3) ----
            #pragma unroll
            for (int s = 0; s < 4; s++) {
                uint32_t qh[4], qlo[4];
                {
                    int row = mrow * 16 + ((g & 1) << 3) + r8;
                    int ch  = 2 * s + (g >> 1);
                    uint32_t off = SWZ(row * 128 + ch * 16);
                    ldsm4(qh,  smb + QHI + off);
                    ldsm4(qlo, smb + QLO + off);
                }
                #pragma unroll
                for (int pp = 0; pp < 2; pp++) {
                    int p = 2 * h + pp;
                    uint32_t kh[4], kl[4];
                    int row = nhalf * 64 + p * 16 + ((g >> 1) << 3) + r8;
                    int ch  = 2 * s + (g & 1);
                    uint32_t off = SWZ(row * 128 + ch * 16);
                    ldsm4(kh, smb + KHI + off);
                    ldsm4(kl, smb + KLO + off);
                    mma_bf16(c[2 * pp],     qlo, kh[0], kh[1]);
                    mma_bf16(c[2 * pp],     qh,  kl[0], kl[1]);
                    mma_bf16(c[2 * pp],     qh,  kh[0], kh[1]);
                    mma_bf16(c[2 * pp + 1], qlo, kh[2], kh[3]);
                    mma_bf16(c[2 * pp + 1], qh,  kl[2], kl[3]);
                    mma_bf16(c[2 * pp + 1], qh,  kh[2], kh[3]);
                }
            }

            // ---- mask + exp + rowsum + store E ----
            #pragma unroll
            for (int jl = 0; jl < 4; jl++) {
                int kc = kb + (4 * h + jl) * 8;
                c[jl][0] = (mql && (!diag || kc     + mn <= qrl)) ? __expf(c[jl][0]) : 0.f;
                c[jl][1] = (mql && (!diag || kc + 1 + mn <= qrl)) ? __expf(c[jl][1]) : 0.f;
                c[jl][2] = (mqh && (!diag || kc     + mn <= qrh)) ? __expf(c[jl][2]) : 0.f;
                c[jl][3] = (mqh && (!diag || kc + 1 + mn <= qrh)) ? __expf(c[jl][3]) : 0.f;
                rsl += c[jl][0] + c[jl][1];
                rsh += c[jl][2] + c[jl][3];
                *(float2*)(E + ((size_t)bh * SEQ + qrl) * SEQ + kc) =
                    make_float2(c[jl][0], c[jl][1]);
                *(float2*)(E + ((size_t)bh * SEQ + qrh) * SEQ + kc) =
                    make_float2(c[jl][2], c[jl][3]);
            }

            // ---- PV: A = E (from regs), B = V^T via ldmatrix.trans ----
            #pragma unroll
            for (int sl = 0; sl < 2; sl++) {
                int s = 2 * h + sl;
                uint32_t ahi[4], alo[4];
                split2(c[2 * sl][0],     c[2 * sl][1],     ahi[0], alo[0]);
                split2(c[2 * sl][2],     c[2 * sl][3],     ahi[1], alo[1]);
                split2(c[2 * sl + 1][0], c[2 * sl + 1][1], ahi[2], alo[2]);
                split2(c[2 * sl + 1][2], c[2 * sl + 1][3], ahi[3], alo[3]);
                int krow = nhalf * 64 + s * 16 + ((g & 1) << 3) + r8;
                #pragma unroll
                for (int p = 0; p < 4; p++) {
                    uint32_t bhr[4], blr[4];
                    int ch = 2 * p + (g >> 1);
                    uint32_t off = SWZ(krow * 128 + ch * 16);
                    ldsm4t(bhr, smb + VHI + off);
                    ldsm4t(blr, smb + VLO + off);
                    mma_bf16(o[2 * p],     alo, bhr[0], bhr[1]);
                    mma_bf16(o[2 * p],     ahi, blr[0], blr[1]);
                    mma_bf16(o[2 * p],     ahi, bhr[0], bhr[1]);
                    mma_bf16(o[2 * p + 1], alo, bhr[2], bhr[3]);
                    mma_bf16(o[2 * p + 1], ahi, blr[2], blr[3]);
                    mma_bf16(o[2 * p + 1], ahi, bhr[2], bhr[3]);
                }
            }
        }
    }

    // ---- rowsums -> l, inv ----
    rsl += __shfl_xor_sync(0xffffffffu, rsl, 1);
    rsl += __shfl_xor_sync(0xffffffffu, rsl, 2);
    rsh += __shfl_xor_sync(0xffffffffu, rsh, 1);
    rsh += __shfl_xor_sync(0xffffffffu, rsh, 2);
    if ((lane & 3) == 0) {
        RS[nhalf * 128 + rl] = rsl;
        RS[nhalf * 128 + rh] = rsh;
    }
    __syncthreads();
    if (tid < 128) {
        float l = RS[tid] + RS[128 + tid];
        g_l[bh * SEQ + q0 + tid] = l;
        INV[tid] = (l > 0.f) ? (1.f / l) : 0.f;
    }
    __syncthreads();

    // ---- cross-warp O reduce (+ scale) and store ----
    const int dcol = 2 * (lane & 3);
    if (nhalf == 1) {
        #pragma unroll
        for (int j = 0; j < 8; j++) {
            *(float2*)(Ob + rl * 68 + j * 8 + dcol) = make_float2(o[j][0], o[j][1]);
            *(float2*)(Ob + rh * 68 + j * 8 + dcol) = make_float2(o[j][2], o[j][3]);
        }
    }
    __syncthreads();
    if (nhalf == 0) {
        float il = INV[rl], ih = INV[rh];
        #pragma unroll
        for (int j = 0; j < 8; j++) {
            float2 p0 = *(float2*)(Ob + rl * 68 + j * 8 + dcol);
            float2 p1 = *(float2*)(Ob + rh * 68 + j * 8 + dcol);
            *(float2*)(O + ((size_t)bh * SEQ + qrl) * HD + j * 8 + dcol) =
                make_float2((o[j][0] + p0.x) * il, (o[j][1] + p0.y) * il);
            *(float2*)(O + ((size_t)bh * SEQ + qrh) * HD + j * 8 + dcol) =
                make_float2((o[j][2] + p1.x) * ih, (o[j][3] + p1.y) * ih);
        }
    }
}

// ---------------------------------------------------------------------------
// K2: P = E / l on the causal part, exact zeros above the diagonal.
// ---------------------------------------------------------------------------
__global__ __launch_bounds__(256) void k_norm(
    const int* __restrict__ mask_now, float* __restrict__ P)
{
    const int row = blockIdx.x;            // bh*SEQ + q
    const int q   = row & (SEQ - 1);
    const float l = g_l[row];
    const float inv = (l > 0.f) ? (1.f / l) : 0.f;
    const int kmax = q - mask_now[0];

    float4* ptr = (float4*)(P + (size_t)row * SEQ);
    for (int t = threadIdx.x; t < SEQ / 4; t += 256) {
        const int k0 = t * 4;
        float4 v;
        if (k0 <= kmax) {
            v = ptr[t];
            v.x *= inv; v.y *= inv; v.z *= inv; v.w *= inv;
        } else {
            v = make_float4(0.f, 0.f, 0.f, 0.f);
        }
        ptr[t] = v;
    }
}

// ---------------------------------------------------------------------------
extern "C" void kernel_launch(void* const* d_in, const int* in_sizes, int n_in,
                              void* d_out, int out_size)
{
    const float* Q        = (const float*)d_in[0];
    const float* K        = (const float*)d_in[1];
    const float* V        = (const float*)d_in[2];
    const float* mask     = (const float*)d_in[3];
    const int*   mask_now = (const int*)d_in[4];

    float* O = (float*)d_out;                      // [B,H,S,D]
    float* P = O + (size_t)NBH * SEQ * HD;         // [B,H,S,S]

    cudaFuncSetAttribute(k_attn, cudaFuncAttributeMaxDynamicSharedMemorySize, 99840);

    k_attn<<<dim3(16, NBH), 512, 99840>>>(Q, K, V, mask, mask_now, P, O);
    k_norm<<<NBH * SEQ, 256>>>(mask_now, P);
}